// round 4
// baseline (speedup 1.0000x reference)
#include <cuda_runtime.h>
#include <math.h>

#define BB 4
#define NN 1024
#define FF 512
#define EE 32
#define HH 8
#define HD 64
#define MM (BB*NN)   // 4096

// ---- scratch (static device globals: allowed; runtime alloc is not) ----
__device__ float g_Q [MM*FF];
__device__ float g_K [MM*FF];
__device__ float g_V [MM*FF];
__device__ float g_AO[MM*FF];
__device__ float g_bias[(size_t)BB*HH*NN*NN];   // [b][h][q][k], mask folded in

// ============================================================================
// SGEMM (NT): C[M,512] = A[M,512] @ W[512,512]^T + bias
// BM=BN=128, BK=16, 256 threads, 8x8 per-thread tile.
// ============================================================================
__global__ __launch_bounds__(256) void sgemm_nt(
    const float* __restrict__ A, const float* __restrict__ W,
    const float* __restrict__ bias, float* __restrict__ C)
{
    const int BK = 16;
    __shared__ float sA[BK][128];
    __shared__ float sB[BK][128];

    const int tid  = threadIdx.x;
    const int m0   = blockIdx.y * 128;
    const int n0   = blockIdx.x * 128;
    const int tx   = tid & 15;
    const int ty   = tid >> 4;
    const int lrow = tid >> 1;        // 0..127
    const int lc4  = (tid & 1) * 2;   // float4 column 0 or 2

    float acc[8][8];
#pragma unroll
    for (int i = 0; i < 8; ++i)
#pragma unroll
        for (int j = 0; j < 8; ++j) acc[i][j] = 0.f;

    for (int k0 = 0; k0 < 512; k0 += BK) {
#pragma unroll
        for (int t = 0; t < 2; ++t) {
            const int c = lc4 + t;
            float4 a = *(const float4*)(A + (size_t)(m0 + lrow) * 512 + k0 + c * 4);
            sA[c*4+0][lrow] = a.x; sA[c*4+1][lrow] = a.y;
            sA[c*4+2][lrow] = a.z; sA[c*4+3][lrow] = a.w;
            float4 b = *(const float4*)(W + (size_t)(n0 + lrow) * 512 + k0 + c * 4);
            sB[c*4+0][lrow] = b.x; sB[c*4+1][lrow] = b.y;
            sB[c*4+2][lrow] = b.z; sB[c*4+3][lrow] = b.w;
        }
        __syncthreads();
#pragma unroll
        for (int k = 0; k < BK; ++k) {
            float af[8], bf[8];
            *(float4*)(af)     = *(const float4*)&sA[k][ty*8];
            *(float4*)(af + 4) = *(const float4*)&sA[k][ty*8 + 4];
            *(float4*)(bf)     = *(const float4*)&sB[k][tx*8];
            *(float4*)(bf + 4) = *(const float4*)&sB[k][tx*8 + 4];
#pragma unroll
            for (int i = 0; i < 8; ++i)
#pragma unroll
                for (int j = 0; j < 8; ++j)
                    acc[i][j] = fmaf(af[i], bf[j], acc[i][j]);
        }
        __syncthreads();
    }

#pragma unroll
    for (int i = 0; i < 8; ++i) {
        const int row = m0 + ty*8 + i;
#pragma unroll
        for (int j4 = 0; j4 < 2; ++j4) {
            const int col = n0 + tx*8 + j4*4;
            float4 o;
            o.x = acc[i][j4*4+0] + bias[col+0];
            o.y = acc[i][j4*4+1] + bias[col+1];
            o.z = acc[i][j4*4+2] + bias[col+2];
            o.w = acc[i][j4*4+3] + bias[col+3];
            *(float4*)(C + (size_t)row * 512 + col) = o;
        }
    }
}

// ============================================================================
// Edge bias: bias[b][h][q][k] = mask ? (edge[b,q,k,:] . We[h,:] + be[h]) : -1e30
// One thread per (b,q,k). HBM-bound (512 MB read + 128 MB write).
// ============================================================================
__global__ __launch_bounds__(256) void edge_bias_kernel(
    const float4* __restrict__ ef, const int* __restrict__ mask,
    const float* __restrict__ We, const float* __restrict__ be,
    float* __restrict__ bias)
{
    __shared__ float sWe[HH][EE];
    __shared__ float sbe[HH];
    if (threadIdx.x < HH * EE) sWe[threadIdx.x >> 5][threadIdx.x & 31] = We[threadIdx.x];
    if (threadIdx.x < HH) sbe[threadIdx.x] = be[threadIdx.x];
    __syncthreads();

    const size_t idx = (size_t)blockIdx.x * blockDim.x + threadIdx.x; // over B*N*N
    const int    k   = (int)(idx & (NN - 1));
    const size_t qb  = idx >> 10;            // b*N + q
    const int    q   = (int)(qb & (NN - 1));
    const int    b   = (int)(qb >> 10);

    float acc[HH];
    if (mask[idx]) {
#pragma unroll
        for (int h = 0; h < HH; ++h) acc[h] = sbe[h];
#pragma unroll
        for (int e4 = 0; e4 < 8; ++e4) {
            float4 v = ef[idx * 8 + e4];
#pragma unroll
            for (int h = 0; h < HH; ++h) {
                acc[h] = fmaf(v.x, sWe[h][e4*4+0], acc[h]);
                acc[h] = fmaf(v.y, sWe[h][e4*4+1], acc[h]);
                acc[h] = fmaf(v.z, sWe[h][e4*4+2], acc[h]);
                acc[h] = fmaf(v.w, sWe[h][e4*4+3], acc[h]);
            }
        }
    } else {
#pragma unroll
        for (int h = 0; h < HH; ++h) acc[h] = -1e30f;
    }
#pragma unroll
    for (int h = 0; h < HH; ++h)
        bias[(((size_t)b * HH + h) * NN + q) * NN + k] = acc[h];
}

// ============================================================================
// Fused flash attention (fp32, online softmax).
// CTA = (q_block=64, head, batch), 128 threads (x=0..15 over k/d, y=0..7 over q).
// Each thread: 8 q-rows x 4 cols. Smem = exactly 48KB static.
// ============================================================================
__global__ __launch_bounds__(128, 4) void attn_kernel(
    const float* __restrict__ Q, const float* __restrict__ K,
    const float* __restrict__ V, const float* __restrict__ bias,
    float* __restrict__ AO)
{
    __shared__ float sQt[HD][64];   // [d][q]  (loaded once)
    __shared__ float sKP[HD][64];   // K as [d][k] during S-gemm; reused as P[q][k]
    __shared__ float sV [64][HD];   // [k][d]

    const int tid = threadIdx.x;
    const int x = tid & 15;         // k-cols (S) / d-cols (O)
    const int y = tid >> 4;         // q-rows
    const int q0 = blockIdx.x * 64;
    const int h  = blockIdx.y;
    const int b  = blockIdx.z;

    const float* Qb = Q + (size_t)(b * NN) * FF + h * HD;
    const float* Kb = K + (size_t)(b * NN) * FF + h * HD;
    const float* Vb = V + (size_t)(b * NN) * FF + h * HD;
    const float* biasb = bias + ((size_t)b * HH + h) * NN * NN;

    // ---- load Q tile, transposed into sQt[d][q] ----
    {
        const int r  = tid >> 1;          // 0..63
        const int c0 = (tid & 1) * 32;
        const float* src = Qb + (size_t)(q0 + r) * FF + c0;
#pragma unroll
        for (int c4 = 0; c4 < 8; ++c4) {
            float4 v = *(const float4*)(src + c4 * 4);
            sQt[c0 + c4*4 + 0][r] = v.x;
            sQt[c0 + c4*4 + 1][r] = v.y;
            sQt[c0 + c4*4 + 2][r] = v.z;
            sQt[c0 + c4*4 + 3][r] = v.w;
        }
    }

    float m_i[8], l_i[8], o[8][4];
#pragma unroll
    for (int i = 0; i < 8; ++i) {
        m_i[i] = -1e38f; l_i[i] = 0.f;
#pragma unroll
        for (int j = 0; j < 4; ++j) o[i][j] = 0.f;
    }

    for (int kt = 0; kt < NN; kt += 64) {
        __syncthreads();   // prior PV done: sKP/sV reusable (also a no-op on iter 0)
        // ---- load K (transposed) and V (direct) tiles ----
        {
            const int r  = tid >> 1;
            const int c0 = (tid & 1) * 32;
            const float* ks = Kb + (size_t)(kt + r) * FF + c0;
            const float* vs = Vb + (size_t)(kt + r) * FF + c0;
#pragma unroll
            for (int c4 = 0; c4 < 8; ++c4) {
                float4 kv = *(const float4*)(ks + c4 * 4);
                sKP[c0 + c4*4 + 0][r] = kv.x;
                sKP[c0 + c4*4 + 1][r] = kv.y;
                sKP[c0 + c4*4 + 2][r] = kv.z;
                sKP[c0 + c4*4 + 3][r] = kv.w;
                float4 vv = *(const float4*)(vs + c4 * 4);
                *(float4*)&sV[r][c0 + c4*4] = vv;
            }
        }
        __syncthreads();

        // ---- S = Q K^T ----
        float s[8][4];
#pragma unroll
        for (int i = 0; i < 8; ++i)
#pragma unroll
            for (int j = 0; j < 4; ++j) s[i][j] = 0.f;
#pragma unroll
        for (int d = 0; d < HD; ++d) {
            float qf[8], kf[4];
            *(float4*)(qf)     = *(const float4*)&sQt[d][y*8];
            *(float4*)(qf + 4) = *(const float4*)&sQt[d][y*8 + 4];
            *(float4*)(kf)     = *(const float4*)&sKP[d][x*4];
#pragma unroll
            for (int i = 0; i < 8; ++i)
#pragma unroll
                for (int j = 0; j < 4; ++j)
                    s[i][j] = fmaf(qf[i], kf[j], s[i][j]);
        }
        __syncthreads();   // all sKP(K) reads done before P overwrites it

        // ---- bias + scale + online softmax; write P into sKP ----
#pragma unroll
        for (int i = 0; i < 8; ++i) {
            float4 bv = *(const float4*)(biasb + (size_t)(q0 + y*8 + i) * NN + kt + x*4);
            s[i][0] = fmaf(s[i][0], 0.125f, bv.x);
            s[i][1] = fmaf(s[i][1], 0.125f, bv.y);
            s[i][2] = fmaf(s[i][2], 0.125f, bv.z);
            s[i][3] = fmaf(s[i][3], 0.125f, bv.w);

            float rmax = fmaxf(fmaxf(s[i][0], s[i][1]), fmaxf(s[i][2], s[i][3]));
#pragma unroll
            for (int off = 1; off < 16; off <<= 1)
                rmax = fmaxf(rmax, __shfl_xor_sync(0xffffffffu, rmax, off));

            const float mnew = fmaxf(m_i[i], rmax);
            const float corr = __expf(m_i[i] - mnew);
            m_i[i] = mnew;

            float psum = 0.f;
#pragma unroll
            for (int j = 0; j < 4; ++j) {
                s[i][j] = __expf(s[i][j] - mnew);
                psum += s[i][j];
            }
#pragma unroll
            for (int off = 1; off < 16; off <<= 1)
                psum += __shfl_xor_sync(0xffffffffu, psum, off);

            l_i[i] = l_i[i] * corr + psum;
#pragma unroll
            for (int j = 0; j < 4; ++j) o[i][j] *= corr;

            // P[q][k]: rows = q (y*8+i), cols = k (x*4..x*4+3), stored into sKP
            float* prow = &sKP[0][0] + (y*8 + i) * 64 + x*4;
            prow[0] = s[i][0]; prow[1] = s[i][1]; prow[2] = s[i][2]; prow[3] = s[i][3];
        }
        __syncthreads();

        // ---- O += P @ V ----
        const float* P = &sKP[0][0];
#pragma unroll
        for (int kk = 0; kk < 64; ++kk) {
            float pf[8], vf[4];
#pragma unroll
            for (int i = 0; i < 8; ++i) pf[i] = P[(y*8 + i) * 64 + kk];
            *(float4*)vf = *(const float4*)&sV[kk][x*4];
#pragma unroll
            for (int i = 0; i < 8; ++i)
#pragma unroll
                for (int j = 0; j < 4; ++j)
                    o[i][j] = fmaf(pf[i], vf[j], o[i][j]);
        }
    }

    // ---- epilogue: normalize, write [b, q, h*64 + d] ----
#pragma unroll
    for (int i = 0; i < 8; ++i) {
        const float inv = 1.0f / l_i[i];
        float4 ov = make_float4(o[i][0]*inv, o[i][1]*inv, o[i][2]*inv, o[i][3]*inv);
        *(float4*)(AO + (size_t)(b*NN + q0 + y*8 + i) * FF + h*HD + x*4) = ov;
    }
}

// ============================================================================
// Launch
// ============================================================================
extern "C" void kernel_launch(void* const* d_in, const int* in_sizes, int n_in,
                              void* d_out, int out_size)
{
    (void)in_sizes; (void)n_in; (void)out_size;
    const float* x   = (const float*)d_in[0];
    const float* ef  = (const float*)d_in[1];
    const int*   msk = (const int*)  d_in[2];
    const float* Wq  = (const float*)d_in[3];
    const float* bq  = (const float*)d_in[4];
    const float* Wk  = (const float*)d_in[5];
    const float* bk  = (const float*)d_in[6];
    const float* Wv  = (const float*)d_in[7];
    const float* bv  = (const float*)d_in[8];
    const float* We  = (const float*)d_in[9];
    const float* be  = (const float*)d_in[10];
    const float* Wo  = (const float*)d_in[11];
    const float* bo  = (const float*)d_in[12];
    float* out = (float*)d_out;

    float *pQ, *pK, *pV, *pAO, *pBias;
    cudaGetSymbolAddress((void**)&pQ,    g_Q);
    cudaGetSymbolAddress((void**)&pK,    g_K);
    cudaGetSymbolAddress((void**)&pV,    g_V);
    cudaGetSymbolAddress((void**)&pAO,   g_AO);
    cudaGetSymbolAddress((void**)&pBias, g_bias);

    dim3 gemm_grid(512 / 128, MM / 128);   // (4, 32)

    sgemm_nt<<<gemm_grid, 256>>>(x, Wq, bq, pQ);
    sgemm_nt<<<gemm_grid, 256>>>(x, Wk, bk, pK);
    sgemm_nt<<<gemm_grid, 256>>>(x, Wv, bv, pV);

    edge_bias_kernel<<<(BB * NN * NN) / 256, 256>>>(
        (const float4*)ef, msk, We, be, pBias);

    attn_kernel<<<dim3(NN / 64, HH, BB), 128>>>(pQ, pK, pV, pBias, pAO);

    sgemm_nt<<<gemm_grid, 256>>>(pAO, Wo, bo, out);
}

// round 6
// speedup vs baseline: 1.2313x; 1.2313x over previous
#include <cuda_runtime.h>
#include <math.h>

#define BB 4
#define NN 1024
#define FF 512
#define EE 32
#define HH 8
#define HD 64
#define MM (BB*NN)   // 4096

// ---- scratch (static device globals: allowed; runtime alloc is not) ----
__device__ float g_Q [MM*FF];
__device__ float g_K [MM*FF];
__device__ float g_V [MM*FF];
__device__ float g_AO[MM*FF];
__device__ float g_bias[(size_t)BB*HH*NN*NN];   // [b][h][q][k], mask folded in

// ============================================================================
// helpers: tf32 split + mma, packed f32x2 fma
// ============================================================================
__device__ __forceinline__ void split_tf32(float x, unsigned& hi, unsigned& lo) {
    asm("cvt.rna.tf32.f32 %0, %1;" : "=r"(hi) : "f"(x));
    float r = x - __uint_as_float(hi);
    asm("cvt.rna.tf32.f32 %0, %1;" : "=r"(lo) : "f"(r));
}

__device__ __forceinline__ void mma_tf32(float (&d)[4], const unsigned (&a)[4],
                                         unsigned b0, unsigned b1) {
    asm volatile(
        "mma.sync.aligned.m16n8k8.row.col.f32.tf32.tf32.f32 "
        "{%0,%1,%2,%3}, {%4,%5,%6,%7}, {%8,%9}, {%0,%1,%2,%3};\n"
        : "+f"(d[0]), "+f"(d[1]), "+f"(d[2]), "+f"(d[3])
        : "r"(a[0]), "r"(a[1]), "r"(a[2]), "r"(a[3]), "r"(b0), "r"(b1));
}

__device__ __forceinline__ unsigned long long pk2(float x, float y) {
    unsigned long long r;
    asm("mov.b64 %0, {%1,%2};" : "=l"(r) : "f"(x), "f"(y));
    return r;
}
__device__ __forceinline__ float2 upk2(unsigned long long v) {
    float x, y;
    asm("mov.b64 {%0,%1}, %2;" : "=f"(x), "=f"(y) : "l"(v));
    return make_float2(x, y);
}
__device__ __forceinline__ unsigned long long fma2(unsigned long long a,
                                                   unsigned long long b,
                                                   unsigned long long c) {
    unsigned long long d;
    asm("fma.rn.f32x2 %0, %1, %2, %3;" : "=l"(d) : "l"(a), "l"(b), "l"(c));
    return d;
}

// ============================================================================
// 3xTF32 GEMM (NT): C[M,512] = A[M,512] @ W[512,512]^T + bias
// BM=128, BN=64, BK=32; 256 threads = 8 warps (4m x 2n), warp tile 32x32.
// blockIdx.z selects one of three (W, bias, C) sets (QKV fused launch).
// ============================================================================
__global__ __launch_bounds__(256) void gemm_tf32x3(
    const float* __restrict__ A,
    const float* __restrict__ W0, const float* __restrict__ W1, const float* __restrict__ W2,
    const float* __restrict__ b0p, const float* __restrict__ b1p, const float* __restrict__ b2p,
    float* __restrict__ C0, float* __restrict__ C1, float* __restrict__ C2)
{
    const float* W    = (blockIdx.z == 0) ? W0  : (blockIdx.z == 1) ? W1  : W2;
    const float* bias = (blockIdx.z == 0) ? b0p : (blockIdx.z == 1) ? b1p : b2p;
    float*       C    = (blockIdx.z == 0) ? C0  : (blockIdx.z == 1) ? C1  : C2;

    __shared__ float sA[128][36];   // pad 4: stride 144B (16-aligned, conflict-free frags)
    __shared__ float sB[64][36];

    const int tid  = threadIdx.x;
    const int lane = tid & 31;
    const int wid  = tid >> 5;
    const int gID  = lane >> 2;     // 0..7
    const int tIG  = lane & 3;      // 0..3
    const int wm   = (wid >> 1) * 32;   // warp m-origin within tile
    const int wn   = (wid & 1) * 32;    // warp n-origin within tile
    const int m0   = blockIdx.y * 128;
    const int n0   = blockIdx.x * 64;

    float d[2][4][4];
#pragma unroll
    for (int mi = 0; mi < 2; ++mi)
#pragma unroll
        for (int ni = 0; ni < 4; ++ni)
#pragma unroll
            for (int r = 0; r < 4; ++r) d[mi][ni][r] = 0.f;

    for (int k0 = 0; k0 < 512; k0 += 32) {
        // cooperative loads: fully coalesced float4, conflict-free STS.128
#pragma unroll
        for (int i = 0; i < 4; ++i) {
            int j = tid + i * 256;
            int row = j >> 3, c = (j & 7) * 4;
            *(float4*)&sA[row][c] = *(const float4*)(A + (size_t)(m0 + row) * 512 + k0 + c);
        }
#pragma unroll
        for (int i = 0; i < 2; ++i) {
            int j = tid + i * 256;
            int row = j >> 3, c = (j & 7) * 4;
            *(float4*)&sB[row][c] = *(const float4*)(W + (size_t)(n0 + row) * 512 + k0 + c);
        }
        __syncthreads();

#pragma unroll
        for (int ks = 0; ks < 4; ++ks) {
            unsigned bh[4][2], bl[4][2];
#pragma unroll
            for (int ni = 0; ni < 4; ++ni) {
                split_tf32(sB[wn + ni * 8 + gID][ks * 8 + tIG],     bh[ni][0], bl[ni][0]);
                split_tf32(sB[wn + ni * 8 + gID][ks * 8 + tIG + 4], bh[ni][1], bl[ni][1]);
            }
#pragma unroll
            for (int mi = 0; mi < 2; ++mi) {
                unsigned ah[4], al[4];
                split_tf32(sA[wm + mi * 16 + gID    ][ks * 8 + tIG],     ah[0], al[0]);
                split_tf32(sA[wm + mi * 16 + gID + 8][ks * 8 + tIG],     ah[1], al[1]);
                split_tf32(sA[wm + mi * 16 + gID    ][ks * 8 + tIG + 4], ah[2], al[2]);
                split_tf32(sA[wm + mi * 16 + gID + 8][ks * 8 + tIG + 4], ah[3], al[3]);
#pragma unroll
                for (int ni = 0; ni < 4; ++ni) {
                    mma_tf32(d[mi][ni], ah, bh[ni][0], bh[ni][1]);
                    mma_tf32(d[mi][ni], ah, bl[ni][0], bl[ni][1]);
                    mma_tf32(d[mi][ni], al, bh[ni][0], bh[ni][1]);
                }
            }
        }
        __syncthreads();
    }

    // epilogue
#pragma unroll
    for (int mi = 0; mi < 2; ++mi) {
#pragma unroll
        for (int ni = 0; ni < 4; ++ni) {
            const int row = m0 + wm + mi * 16 + gID;
            const int col = n0 + wn + ni * 8 + 2 * tIG;
            float2 bb = *(const float2*)&bias[col];
            float2 o0 = make_float2(d[mi][ni][0] + bb.x, d[mi][ni][1] + bb.y);
            float2 o1 = make_float2(d[mi][ni][2] + bb.x, d[mi][ni][3] + bb.y);
            *(float2*)&C[(size_t)row * 512 + col]       = o0;
            *(float2*)&C[(size_t)(row + 8) * 512 + col] = o1;
        }
    }
}

// ============================================================================
// Edge bias (coalesced): stage 256 rows of edge features through smem,
// one thread per (b,q,k) row, packed f32x2 FMAs over head pairs.
// bias[b][h][q][k] = mask ? edge . We[h] + be[h] : -1e30
// ============================================================================
__global__ __launch_bounds__(256) void edge_bias_kernel(
    const float4* __restrict__ ef4, const int* __restrict__ mask,
    const float* __restrict__ We, const float* __restrict__ be,
    float* __restrict__ bias)
{
    __shared__ float sE[256 * 33];              // 256 rows x 32, stride 33 (conflict-free)
    __shared__ unsigned long long sW2[EE][4];   // [e][head-pair]
    __shared__ float sbe[HH];

    const int t = threadIdx.x;
    if (t < EE * 4) {
        int e = t >> 2, p = t & 3;
        sW2[e][p] = pk2(We[(2 * p) * EE + e], We[(2 * p + 1) * EE + e]);
    }
    if (t < HH) sbe[t] = be[t];

    const size_t row0 = (size_t)blockIdx.x * 256;    // base (b*N+q)*N + k
    const size_t base4 = row0 * 8;

#pragma unroll
    for (int i = 0; i < 8; ++i) {
        int j = t + i * 256;
        float4 v = ef4[base4 + j];                   // fully coalesced
        float* dst = &sE[(j >> 3) * 33 + (j & 7) * 4];
        dst[0] = v.x; dst[1] = v.y; dst[2] = v.z; dst[3] = v.w;
    }
    __syncthreads();

    const int mk = mask[row0 + t];

    unsigned long long acc[4];
#pragma unroll
    for (int p = 0; p < 4; ++p) acc[p] = pk2(sbe[2 * p], sbe[2 * p + 1]);

    const float* myrow = &sE[t * 33];
#pragma unroll
    for (int e = 0; e < EE; ++e) {
        float v = myrow[e];                          // bank (t+e)%32: conflict-free
        unsigned long long v2 = pk2(v, v);
#pragma unroll
        for (int p = 0; p < 4; ++p) acc[p] = fma2(v2, sW2[e][p], acc[p]);
    }

    const size_t kq = row0 + t;
    const int k = (int)(kq & (NN - 1));
    const size_t bq = kq >> 10;
    const int q = (int)(bq & (NN - 1));
    const int b = (int)(bq >> 10);

#pragma unroll
    for (int p = 0; p < 4; ++p) {
        float2 o = upk2(acc[p]);
        float o0 = mk ? o.x : -1e30f;
        float o1 = mk ? o.y : -1e30f;
        bias[(((size_t)b * HH + 2 * p    ) * NN + q) * NN + k] = o0;
        bias[(((size_t)b * HH + 2 * p + 1) * NN + q) * NN + k] = o1;
    }
}

// ============================================================================
// Fused flash attention (fp32, online softmax) — unchanged (validated R4).
// ============================================================================
__global__ __launch_bounds__(128, 4) void attn_kernel(
    const float* __restrict__ Q, const float* __restrict__ K,
    const float* __restrict__ V, const float* __restrict__ bias,
    float* __restrict__ AO)
{
    __shared__ float sQt[HD][64];
    __shared__ float sKP[HD][64];
    __shared__ float sV [64][HD];

    const int tid = threadIdx.x;
    const int x = tid & 15;
    const int y = tid >> 4;
    const int q0 = blockIdx.x * 64;
    const int h  = blockIdx.y;
    const int b  = blockIdx.z;

    const float* Qb = Q + (size_t)(b * NN) * FF + h * HD;
    const float* Kb = K + (size_t)(b * NN) * FF + h * HD;
    const float* Vb = V + (size_t)(b * NN) * FF + h * HD;
    const float* biasb = bias + ((size_t)b * HH + h) * NN * NN;

    {
        const int r  = tid >> 1;
        const int c0 = (tid & 1) * 32;
        const float* src = Qb + (size_t)(q0 + r) * FF + c0;
#pragma unroll
        for (int c4 = 0; c4 < 8; ++c4) {
            float4 v = *(const float4*)(src + c4 * 4);
            sQt[c0 + c4*4 + 0][r] = v.x;
            sQt[c0 + c4*4 + 1][r] = v.y;
            sQt[c0 + c4*4 + 2][r] = v.z;
            sQt[c0 + c4*4 + 3][r] = v.w;
        }
    }

    float m_i[8], l_i[8], o[8][4];
#pragma unroll
    for (int i = 0; i < 8; ++i) {
        m_i[i] = -1e38f; l_i[i] = 0.f;
#pragma unroll
        for (int j = 0; j < 4; ++j) o[i][j] = 0.f;
    }

    for (int kt = 0; kt < NN; kt += 64) {
        __syncthreads();
        {
            const int r  = tid >> 1;
            const int c0 = (tid & 1) * 32;
            const float* ks = Kb + (size_t)(kt + r) * FF + c0;
            const float* vs = Vb + (size_t)(kt + r) * FF + c0;
#pragma unroll
            for (int c4 = 0; c4 < 8; ++c4) {
                float4 kv = *(const float4*)(ks + c4 * 4);
                sKP[c0 + c4*4 + 0][r] = kv.x;
                sKP[c0 + c4*4 + 1][r] = kv.y;
                sKP[c0 + c4*4 + 2][r] = kv.z;
                sKP[c0 + c4*4 + 3][r] = kv.w;
                float4 vv = *(const float4*)(vs + c4 * 4);
                *(float4*)&sV[r][c0 + c4*4] = vv;
            }
        }
        __syncthreads();

        float s[8][4];
#pragma unroll
        for (int i = 0; i < 8; ++i)
#pragma unroll
            for (int j = 0; j < 4; ++j) s[i][j] = 0.f;
#pragma unroll
        for (int d = 0; d < HD; ++d) {
            float qf[8], kf[4];
            *(float4*)(qf)     = *(const float4*)&sQt[d][y*8];
            *(float4*)(qf + 4) = *(const float4*)&sQt[d][y*8 + 4];
            *(float4*)(kf)     = *(const float4*)&sKP[d][x*4];
#pragma unroll
            for (int i = 0; i < 8; ++i)
#pragma unroll
                for (int j = 0; j < 4; ++j)
                    s[i][j] = fmaf(qf[i], kf[j], s[i][j]);
        }
        __syncthreads();

#pragma unroll
        for (int i = 0; i < 8; ++i) {
            float4 bv = *(const float4*)(biasb + (size_t)(q0 + y*8 + i) * NN + kt + x*4);
            s[i][0] = fmaf(s[i][0], 0.125f, bv.x);
            s[i][1] = fmaf(s[i][1], 0.125f, bv.y);
            s[i][2] = fmaf(s[i][2], 0.125f, bv.z);
            s[i][3] = fmaf(s[i][3], 0.125f, bv.w);

            float rmax = fmaxf(fmaxf(s[i][0], s[i][1]), fmaxf(s[i][2], s[i][3]));
#pragma unroll
            for (int off = 1; off < 16; off <<= 1)
                rmax = fmaxf(rmax, __shfl_xor_sync(0xffffffffu, rmax, off));

            const float mnew = fmaxf(m_i[i], rmax);
            const float corr = __expf(m_i[i] - mnew);
            m_i[i] = mnew;

            float psum = 0.f;
#pragma unroll
            for (int j = 0; j < 4; ++j) {
                s[i][j] = __expf(s[i][j] - mnew);
                psum += s[i][j];
            }
#pragma unroll
            for (int off = 1; off < 16; off <<= 1)
                psum += __shfl_xor_sync(0xffffffffu, psum, off);

            l_i[i] = l_i[i] * corr + psum;
#pragma unroll
            for (int j = 0; j < 4; ++j) o[i][j] *= corr;

            float* prow = &sKP[0][0] + (y*8 + i) * 64 + x*4;
            prow[0] = s[i][0]; prow[1] = s[i][1]; prow[2] = s[i][2]; prow[3] = s[i][3];
        }
        __syncthreads();

        const float* P = &sKP[0][0];
#pragma unroll
        for (int kk = 0; kk < 64; ++kk) {
            float pf[8], vf[4];
#pragma unroll
            for (int i = 0; i < 8; ++i) pf[i] = P[(y*8 + i) * 64 + kk];
            *(float4*)vf = *(const float4*)&sV[kk][x*4];
#pragma unroll
            for (int i = 0; i < 8; ++i)
#pragma unroll
                for (int j = 0; j < 4; ++j)
                    o[i][j] = fmaf(pf[i], vf[j], o[i][j]);
        }
    }

#pragma unroll
    for (int i = 0; i < 8; ++i) {
        const float inv = 1.0f / l_i[i];
        float4 ov = make_float4(o[i][0]*inv, o[i][1]*inv, o[i][2]*inv, o[i][3]*inv);
        *(float4*)(AO + (size_t)(b*NN + q0 + y*8 + i) * FF + h*HD + x*4) = ov;
    }
}

// ============================================================================
// Launch
// ============================================================================
extern "C" void kernel_launch(void* const* d_in, const int* in_sizes, int n_in,
                              void* d_out, int out_size)
{
    (void)in_sizes; (void)n_in; (void)out_size;
    const float* x   = (const float*)d_in[0];
    const float* ef  = (const float*)d_in[1];
    const int*   msk = (const int*)  d_in[2];
    const float* Wq  = (const float*)d_in[3];
    const float* bq  = (const float*)d_in[4];
    const float* Wk  = (const float*)d_in[5];
    const float* bk  = (const float*)d_in[6];
    const float* Wv  = (const float*)d_in[7];
    const float* bv  = (const float*)d_in[8];
    const float* We  = (const float*)d_in[9];
    const float* be  = (const float*)d_in[10];
    const float* Wo  = (const float*)d_in[11];
    const float* bo  = (const float*)d_in[12];
    float* out = (float*)d_out;

    float *pQ, *pK, *pV, *pAO, *pBias;
    cudaGetSymbolAddress((void**)&pQ,    g_Q);
    cudaGetSymbolAddress((void**)&pK,    g_K);
    cudaGetSymbolAddress((void**)&pV,    g_V);
    cudaGetSymbolAddress((void**)&pAO,   g_AO);
    cudaGetSymbolAddress((void**)&pBias, g_bias);

    // QKV fused: grid (N/64, M/128, 3)
    dim3 gqkv(512 / 64, MM / 128, 3);
    gemm_tf32x3<<<gqkv, 256>>>(x, Wq, Wk, Wv, bq, bk, bv, pQ, pK, pV);

    edge_bias_kernel<<<(BB * NN * NN) / 256, 256>>>(
        (const float4*)ef, msk, We, be, pBias);

    attn_kernel<<<dim3(NN / 64, HH, BB), 128>>>(pQ, pK, pV, pBias, pAO);

    dim3 go(512 / 64, MM / 128, 1);
    gemm_tf32x3<<<go, 256>>>(pAO, Wo, Wo, Wo, bo, bo, bo, out, out, out);
}

// round 7
// speedup vs baseline: 1.3109x; 1.0647x over previous
#include <cuda_runtime.h>
#include <math.h>

#define BB 4
#define NN 1024
#define FF 512
#define EE 32
#define HH 8
#define HD 64
#define MM (BB*NN)   // 4096

// ---- scratch (static device globals: allowed; runtime alloc is not) ----
__device__ float g_Q [MM*FF];
__device__ float g_K [MM*FF];
__device__ float g_V [MM*FF];
__device__ float g_AO[MM*FF];
__device__ float g_bias[(size_t)BB*HH*NN*NN];   // [b][h][q][k], mask folded in

// ============================================================================
// helpers: tf32 split + mma, packed f32x2 fma
// ============================================================================
__device__ __forceinline__ void split_tf32(float x, unsigned& hi, unsigned& lo) {
    asm("cvt.rna.tf32.f32 %0, %1;" : "=r"(hi) : "f"(x));
    float r = x - __uint_as_float(hi);
    asm("cvt.rna.tf32.f32 %0, %1;" : "=r"(lo) : "f"(r));
}

__device__ __forceinline__ void mma_tf32(float (&d)[4], const unsigned (&a)[4],
                                         unsigned b0, unsigned b1) {
    asm volatile(
        "mma.sync.aligned.m16n8k8.row.col.f32.tf32.tf32.f32 "
        "{%0,%1,%2,%3}, {%4,%5,%6,%7}, {%8,%9}, {%0,%1,%2,%3};\n"
        : "+f"(d[0]), "+f"(d[1]), "+f"(d[2]), "+f"(d[3])
        : "r"(a[0]), "r"(a[1]), "r"(a[2]), "r"(a[3]), "r"(b0), "r"(b1));
}

__device__ __forceinline__ unsigned long long pk2(float x, float y) {
    unsigned long long r;
    asm("mov.b64 %0, {%1,%2};" : "=l"(r) : "f"(x), "f"(y));
    return r;
}
__device__ __forceinline__ float2 upk2(unsigned long long v) {
    float x, y;
    asm("mov.b64 {%0,%1}, %2;" : "=f"(x), "=f"(y) : "l"(v));
    return make_float2(x, y);
}
__device__ __forceinline__ unsigned long long fma2(unsigned long long a,
                                                   unsigned long long b,
                                                   unsigned long long c) {
    unsigned long long d;
    asm("fma.rn.f32x2 %0, %1, %2, %3;" : "=l"(d) : "l"(a), "l"(b), "l"(c));
    return d;
}

// ============================================================================
// 3xTF32 GEMM (NT): C[M,512] = A[M,512] @ W[512,512]^T + bias  (validated R6)
// ============================================================================
__global__ __launch_bounds__(256) void gemm_tf32x3(
    const float* __restrict__ A,
    const float* __restrict__ W0, const float* __restrict__ W1, const float* __restrict__ W2,
    const float* __restrict__ b0p, const float* __restrict__ b1p, const float* __restrict__ b2p,
    float* __restrict__ C0, float* __restrict__ C1, float* __restrict__ C2)
{
    const float* W    = (blockIdx.z == 0) ? W0  : (blockIdx.z == 1) ? W1  : W2;
    const float* bias = (blockIdx.z == 0) ? b0p : (blockIdx.z == 1) ? b1p : b2p;
    float*       C    = (blockIdx.z == 0) ? C0  : (blockIdx.z == 1) ? C1  : C2;

    __shared__ float sA[128][36];
    __shared__ float sB[64][36];

    const int tid  = threadIdx.x;
    const int lane = tid & 31;
    const int wid  = tid >> 5;
    const int gID  = lane >> 2;
    const int tIG  = lane & 3;
    const int wm   = (wid >> 1) * 32;
    const int wn   = (wid & 1) * 32;
    const int m0   = blockIdx.y * 128;
    const int n0   = blockIdx.x * 64;

    float d[2][4][4];
#pragma unroll
    for (int mi = 0; mi < 2; ++mi)
#pragma unroll
        for (int ni = 0; ni < 4; ++ni)
#pragma unroll
            for (int r = 0; r < 4; ++r) d[mi][ni][r] = 0.f;

    for (int k0 = 0; k0 < 512; k0 += 32) {
#pragma unroll
        for (int i = 0; i < 4; ++i) {
            int j = tid + i * 256;
            int row = j >> 3, c = (j & 7) * 4;
            *(float4*)&sA[row][c] = *(const float4*)(A + (size_t)(m0 + row) * 512 + k0 + c);
        }
#pragma unroll
        for (int i = 0; i < 2; ++i) {
            int j = tid + i * 256;
            int row = j >> 3, c = (j & 7) * 4;
            *(float4*)&sB[row][c] = *(const float4*)(W + (size_t)(n0 + row) * 512 + k0 + c);
        }
        __syncthreads();

#pragma unroll
        for (int ks = 0; ks < 4; ++ks) {
            unsigned bh[4][2], bl[4][2];
#pragma unroll
            for (int ni = 0; ni < 4; ++ni) {
                split_tf32(sB[wn + ni * 8 + gID][ks * 8 + tIG],     bh[ni][0], bl[ni][0]);
                split_tf32(sB[wn + ni * 8 + gID][ks * 8 + tIG + 4], bh[ni][1], bl[ni][1]);
            }
#pragma unroll
            for (int mi = 0; mi < 2; ++mi) {
                unsigned ah[4], al[4];
                split_tf32(sA[wm + mi * 16 + gID    ][ks * 8 + tIG],     ah[0], al[0]);
                split_tf32(sA[wm + mi * 16 + gID + 8][ks * 8 + tIG],     ah[1], al[1]);
                split_tf32(sA[wm + mi * 16 + gID    ][ks * 8 + tIG + 4], ah[2], al[2]);
                split_tf32(sA[wm + mi * 16 + gID + 8][ks * 8 + tIG + 4], ah[3], al[3]);
#pragma unroll
                for (int ni = 0; ni < 4; ++ni) {
                    mma_tf32(d[mi][ni], ah, bh[ni][0], bh[ni][1]);
                    mma_tf32(d[mi][ni], ah, bl[ni][0], bl[ni][1]);
                    mma_tf32(d[mi][ni], al, bh[ni][0], bh[ni][1]);
                }
            }
        }
        __syncthreads();
    }

#pragma unroll
    for (int mi = 0; mi < 2; ++mi) {
#pragma unroll
        for (int ni = 0; ni < 4; ++ni) {
            const int row = m0 + wm + mi * 16 + gID;
            const int col = n0 + wn + ni * 8 + 2 * tIG;
            float2 bb = *(const float2*)&bias[col];
            float2 o0 = make_float2(d[mi][ni][0] + bb.x, d[mi][ni][1] + bb.y);
            float2 o1 = make_float2(d[mi][ni][2] + bb.x, d[mi][ni][3] + bb.y);
            *(float2*)&C[(size_t)row * 512 + col]       = o0;
            *(float2*)&C[(size_t)(row + 8) * 512 + col] = o1;
        }
    }
}

// ============================================================================
// Edge bias (coalesced, smem-staged) — validated R6.
// ============================================================================
__global__ __launch_bounds__(256) void edge_bias_kernel(
    const float4* __restrict__ ef4, const int* __restrict__ mask,
    const float* __restrict__ We, const float* __restrict__ be,
    float* __restrict__ bias)
{
    __shared__ float sE[256 * 33];
    __shared__ unsigned long long sW2[EE][4];
    __shared__ float sbe[HH];

    const int t = threadIdx.x;
    if (t < EE * 4) {
        int e = t >> 2, p = t & 3;
        sW2[e][p] = pk2(We[(2 * p) * EE + e], We[(2 * p + 1) * EE + e]);
    }
    if (t < HH) sbe[t] = be[t];

    const size_t row0 = (size_t)blockIdx.x * 256;
    const size_t base4 = row0 * 8;

#pragma unroll
    for (int i = 0; i < 8; ++i) {
        int j = t + i * 256;
        float4 v = ef4[base4 + j];
        float* dst = &sE[(j >> 3) * 33 + (j & 7) * 4];
        dst[0] = v.x; dst[1] = v.y; dst[2] = v.z; dst[3] = v.w;
    }
    __syncthreads();

    const int mk = mask[row0 + t];

    unsigned long long acc[4];
#pragma unroll
    for (int p = 0; p < 4; ++p) acc[p] = pk2(sbe[2 * p], sbe[2 * p + 1]);

    const float* myrow = &sE[t * 33];
#pragma unroll
    for (int e = 0; e < EE; ++e) {
        float v = myrow[e];
        unsigned long long v2 = pk2(v, v);
#pragma unroll
        for (int p = 0; p < 4; ++p) acc[p] = fma2(v2, sW2[e][p], acc[p]);
    }

    const size_t kq = row0 + t;
    const int k = (int)(kq & (NN - 1));
    const size_t bq = kq >> 10;
    const int q = (int)(bq & (NN - 1));
    const int b = (int)(bq >> 10);

#pragma unroll
    for (int p = 0; p < 4; ++p) {
        float2 o = upk2(acc[p]);
        float o0 = mk ? o.x : -1e30f;
        float o1 = mk ? o.y : -1e30f;
        bias[(((size_t)b * HH + 2 * p    ) * NN + q) * NN + k] = o0;
        bias[(((size_t)b * HH + 2 * p + 1) * NN + q) * NN + k] = o1;
    }
}

// ============================================================================
// Flash attention on tensor cores (3xTF32 m16n8k8 for S=QK^T and O+=PV).
// CTA = (q_block 64, head, batch); 4 warps; warp owns 16 q-rows x 64 keys.
// Smem (dynamic, 52.2KB): sQ[64][68], sKP[64][68] (K then P), sVt[64][68].
// Stride 68: A-frag reads bank=4*gID+tIG, B-frag reads bank=4*gID+tIG
// (V transposed) -> conflict-free.
// ============================================================================
#define AST 68
#define SMEM_ATTN (3 * 64 * AST * 4)

__global__ __launch_bounds__(128, 4) void attn_mma(
    const float* __restrict__ Q, const float* __restrict__ K,
    const float* __restrict__ V, const float* __restrict__ bias,
    float* __restrict__ AO)
{
    extern __shared__ float sm[];
    float* sQ  = sm;
    float* sKP = sm + 64 * AST;
    float* sVt = sm + 2 * 64 * AST;

    const int tid  = threadIdx.x;
    const int lane = tid & 31;
    const int wid  = tid >> 5;
    const int gID  = lane >> 2;    // 0..7
    const int tIG  = lane & 3;     // 0..3
    const int wq   = wid * 16;     // warp's q-row origin in tile
    const int q0   = blockIdx.x * 64;
    const int h    = blockIdx.y;
    const int b    = blockIdx.z;

    const float* Qb = Q + (size_t)(b * NN) * FF + h * HD;
    const float* Kb = K + (size_t)(b * NN) * FF + h * HD;
    const float* Vb = V + (size_t)(b * NN) * FF + h * HD;
    const float* biasb = bias + ((size_t)b * HH + h) * NN * NN;

    // ---- load Q tile once: sQ[q][d] ----
    {
        const int r  = tid >> 1;
        const int c0 = (tid & 1) * 32;
        const float* src = Qb + (size_t)(q0 + r) * FF + c0;
#pragma unroll
        for (int c4 = 0; c4 < 8; ++c4)
            *(float4*)&sQ[r * AST + c0 + c4 * 4] = *(const float4*)(src + c4 * 4);
    }

    float m0 = -1e38f, m1 = -1e38f, l0 = 0.f, l1 = 0.f;
    float oacc[8][4];
#pragma unroll
    for (int ni = 0; ni < 8; ++ni)
#pragma unroll
        for (int r = 0; r < 4; ++r) oacc[ni][r] = 0.f;

    const int rowA = wq + gID;      // local q row of c0/c1
    const int rowB = wq + gID + 8;  // local q row of c2/c3

    for (int kt = 0; kt < NN; kt += 64) {
        __syncthreads();   // prev iter's P/V reads done; Q store (iter 0) synced below
        // ---- load K -> sKP[key][d], V -> sVt[d][key] ----
        {
            const int r  = tid >> 1;
            const int c0 = (tid & 1) * 32;
            const float* ks = Kb + (size_t)(kt + r) * FF + c0;
            const float* vs = Vb + (size_t)(kt + r) * FF + c0;
#pragma unroll
            for (int c4 = 0; c4 < 8; ++c4) {
                *(float4*)&sKP[r * AST + c0 + c4 * 4] = *(const float4*)(ks + c4 * 4);
                float4 vv = *(const float4*)(vs + c4 * 4);
                sVt[(c0 + c4*4 + 0) * AST + r] = vv.x;
                sVt[(c0 + c4*4 + 1) * AST + r] = vv.y;
                sVt[(c0 + c4*4 + 2) * AST + r] = vv.z;
                sVt[(c0 + c4*4 + 3) * AST + r] = vv.w;
            }
        }
        __syncthreads();

        // ---- S = Q K^T  (rows=q, cols=key) ----
        float sacc[8][4];
#pragma unroll
        for (int ni = 0; ni < 8; ++ni)
#pragma unroll
            for (int r = 0; r < 4; ++r) sacc[ni][r] = 0.f;

#pragma unroll
        for (int ks = 0; ks < 8; ++ks) {
            unsigned ah[4], al[4];
            split_tf32(sQ[rowA * AST + ks*8 + tIG],     ah[0], al[0]);
            split_tf32(sQ[rowB * AST + ks*8 + tIG],     ah[1], al[1]);
            split_tf32(sQ[rowA * AST + ks*8 + tIG + 4], ah[2], al[2]);
            split_tf32(sQ[rowB * AST + ks*8 + tIG + 4], ah[3], al[3]);
#pragma unroll
            for (int ni = 0; ni < 8; ++ni) {
                unsigned bh0, bl0, bh1, bl1;
                split_tf32(sKP[(ni*8 + gID) * AST + ks*8 + tIG],     bh0, bl0);
                split_tf32(sKP[(ni*8 + gID) * AST + ks*8 + tIG + 4], bh1, bl1);
                mma_tf32(sacc[ni], ah, bh0, bh1);
                mma_tf32(sacc[ni], ah, bl0, bl1);
                mma_tf32(sacc[ni], al, bh0, bh1);
            }
        }

        // ---- bias + scale + online softmax (regs; rows rowA, rowB) ----
        const float* br0 = biasb + (size_t)(q0 + rowA) * NN + kt;
        const float* br1 = biasb + (size_t)(q0 + rowB) * NN + kt;
        float mx0 = -1e38f, mx1 = -1e38f;
#pragma unroll
        for (int ni = 0; ni < 8; ++ni) {
            float2 b0v = *(const float2*)&br0[ni*8 + 2*tIG];
            float2 b1v = *(const float2*)&br1[ni*8 + 2*tIG];
            sacc[ni][0] = fmaf(sacc[ni][0], 0.125f, b0v.x);
            sacc[ni][1] = fmaf(sacc[ni][1], 0.125f, b0v.y);
            sacc[ni][2] = fmaf(sacc[ni][2], 0.125f, b1v.x);
            sacc[ni][3] = fmaf(sacc[ni][3], 0.125f, b1v.y);
            mx0 = fmaxf(mx0, fmaxf(sacc[ni][0], sacc[ni][1]));
            mx1 = fmaxf(mx1, fmaxf(sacc[ni][2], sacc[ni][3]));
        }
        mx0 = fmaxf(mx0, __shfl_xor_sync(0xffffffffu, mx0, 1));
        mx0 = fmaxf(mx0, __shfl_xor_sync(0xffffffffu, mx0, 2));
        mx1 = fmaxf(mx1, __shfl_xor_sync(0xffffffffu, mx1, 1));
        mx1 = fmaxf(mx1, __shfl_xor_sync(0xffffffffu, mx1, 2));

        const float mn0 = fmaxf(m0, mx0), mn1 = fmaxf(m1, mx1);
        const float c0f = __expf(m0 - mn0), c1f = __expf(m1 - mn1);
        m0 = mn0; m1 = mn1;

        float ps0 = 0.f, ps1 = 0.f;
#pragma unroll
        for (int ni = 0; ni < 8; ++ni) {
            sacc[ni][0] = __expf(sacc[ni][0] - mn0); ps0 += sacc[ni][0];
            sacc[ni][1] = __expf(sacc[ni][1] - mn0); ps0 += sacc[ni][1];
            sacc[ni][2] = __expf(sacc[ni][2] - mn1); ps1 += sacc[ni][2];
            sacc[ni][3] = __expf(sacc[ni][3] - mn1); ps1 += sacc[ni][3];
        }
        ps0 += __shfl_xor_sync(0xffffffffu, ps0, 1);
        ps0 += __shfl_xor_sync(0xffffffffu, ps0, 2);
        ps1 += __shfl_xor_sync(0xffffffffu, ps1, 1);
        ps1 += __shfl_xor_sync(0xffffffffu, ps1, 2);
        l0 = l0 * c0f + ps0;
        l1 = l1 * c1f + ps1;

#pragma unroll
        for (int ni = 0; ni < 8; ++ni) {
            oacc[ni][0] *= c0f; oacc[ni][1] *= c0f;
            oacc[ni][2] *= c1f; oacc[ni][3] *= c1f;
        }

        // ---- write P into sKP (after ALL warps finished reading K) ----
        __syncthreads();
#pragma unroll
        for (int ni = 0; ni < 8; ++ni) {
            *(float2*)&sKP[rowA * AST + ni*8 + 2*tIG] = make_float2(sacc[ni][0], sacc[ni][1]);
            *(float2*)&sKP[rowB * AST + ni*8 + 2*tIG] = make_float2(sacc[ni][2], sacc[ni][3]);
        }
        __syncwarp();   // warp reads only its own P rows

        // ---- O += P V  (rows=q, k=key, cols=d) ----
#pragma unroll
        for (int ks = 0; ks < 8; ++ks) {
            unsigned ah[4], al[4];
            split_tf32(sKP[rowA * AST + ks*8 + tIG],     ah[0], al[0]);
            split_tf32(sKP[rowB * AST + ks*8 + tIG],     ah[1], al[1]);
            split_tf32(sKP[rowA * AST + ks*8 + tIG + 4], ah[2], al[2]);
            split_tf32(sKP[rowB * AST + ks*8 + tIG + 4], ah[3], al[3]);
#pragma unroll
            for (int ni = 0; ni < 8; ++ni) {
                unsigned bh0, bl0, bh1, bl1;
                split_tf32(sVt[(ni*8 + gID) * AST + ks*8 + tIG],     bh0, bl0);
                split_tf32(sVt[(ni*8 + gID) * AST + ks*8 + tIG + 4], bh1, bl1);
                mma_tf32(oacc[ni], ah, bh0, bh1);
                mma_tf32(oacc[ni], ah, bl0, bl1);
                mma_tf32(oacc[ni], al, bh0, bh1);
            }
        }
    }

    // ---- epilogue: normalize, write [b, q, h*64 + d] ----
    const float i0 = 1.0f / l0, i1 = 1.0f / l1;
    float* o0 = AO + (size_t)(b*NN + q0 + rowA) * FF + h * HD;
    float* o1 = AO + (size_t)(b*NN + q0 + rowB) * FF + h * HD;
#pragma unroll
    for (int ni = 0; ni < 8; ++ni) {
        *(float2*)&o0[ni*8 + 2*tIG] = make_float2(oacc[ni][0] * i0, oacc[ni][1] * i0);
        *(float2*)&o1[ni*8 + 2*tIG] = make_float2(oacc[ni][2] * i1, oacc[ni][3] * i1);
    }
}

// ============================================================================
// Launch
// ============================================================================
extern "C" void kernel_launch(void* const* d_in, const int* in_sizes, int n_in,
                              void* d_out, int out_size)
{
    (void)in_sizes; (void)n_in; (void)out_size;
    const float* x   = (const float*)d_in[0];
    const float* ef  = (const float*)d_in[1];
    const int*   msk = (const int*)  d_in[2];
    const float* Wq  = (const float*)d_in[3];
    const float* bq  = (const float*)d_in[4];
    const float* Wk  = (const float*)d_in[5];
    const float* bk  = (const float*)d_in[6];
    const float* Wv  = (const float*)d_in[7];
    const float* bv  = (const float*)d_in[8];
    const float* We  = (const float*)d_in[9];
    const float* be  = (const float*)d_in[10];
    const float* Wo  = (const float*)d_in[11];
    const float* bo  = (const float*)d_in[12];
    float* out = (float*)d_out;

    float *pQ, *pK, *pV, *pAO, *pBias;
    cudaGetSymbolAddress((void**)&pQ,    g_Q);
    cudaGetSymbolAddress((void**)&pK,    g_K);
    cudaGetSymbolAddress((void**)&pV,    g_V);
    cudaGetSymbolAddress((void**)&pAO,   g_AO);
    cudaGetSymbolAddress((void**)&pBias, g_bias);

    static int smem_set = 0;
    if (!smem_set) {
        cudaFuncSetAttribute(attn_mma, cudaFuncAttributeMaxDynamicSharedMemorySize,
                             SMEM_ATTN);
        smem_set = 1;
    }

    // QKV fused: grid (N/64, M/128, 3)
    dim3 gqkv(512 / 64, MM / 128, 3);
    gemm_tf32x3<<<gqkv, 256>>>(x, Wq, Wk, Wv, bq, bk, bv, pQ, pK, pV);

    edge_bias_kernel<<<(BB * NN * NN) / 256, 256>>>(
        (const float4*)ef, msk, We, be, pBias);

    attn_mma<<<dim3(NN / 64, HH, BB), 128, SMEM_ATTN>>>(pQ, pK, pV, pBias, pAO);

    dim3 go(512 / 64, MM / 128, 1);
    gemm_tf32x3<<<go, 256>>>(pAO, Wo, Wo, Wo, bo, bo, bo, out, out, out);
}